// round 2
// baseline (speedup 1.0000x reference)
#include <cuda_runtime.h>
#include <cstdint>
#include <cstddef>

#define Bn 256
#define Ln 1024
#define Vn 40
#define Hn 128

// 134 MB scratch for the hidden-state sequence [B, L, H] (alloc-free rule).
__device__ float g_hseq[(size_t)Bn * Ln * Hn];

// ---- packed f32x2 helpers (FFMA2 only reachable via PTX) ----
__device__ __forceinline__ unsigned long long ffma2(unsigned long long a,
                                                    unsigned long long b,
                                                    unsigned long long c) {
    unsigned long long d;
    asm("fma.rn.f32x2 %0, %1, %2, %3;" : "=l"(d) : "l"(a), "l"(b), "l"(c));
    return d;
}
__device__ __forceinline__ unsigned long long add2(unsigned long long a,
                                                   unsigned long long b) {
    unsigned long long d;
    asm("add.rn.f32x2 %0, %1, %2;" : "=l"(d) : "l"(a), "l"(b));
    return d;
}
__device__ __forceinline__ float plo(unsigned long long a) {
    return __int_as_float((int)(unsigned)(a & 0xffffffffull));
}
__device__ __forceinline__ float phi(unsigned long long a) {
    return __int_as_float((int)(unsigned)(a >> 32));
}
__device__ __forceinline__ float tanh_fast(float x) {
    float r;
    asm("tanh.approx.f32 %0, %1;" : "=f"(r) : "f"(x));
    return r;
}

// =====================================================================
// Phase 1: recurrence. 128 CTAs, 128 threads; each CTA owns TWO batch
// rows; thread j computes element j of both rows (shared Wh registers,
// 8 independent FFMA2 chains, two interleaved tails).
// =====================================================================
__global__ void __launch_bounds__(Hn) rnn_scan_kernel(
    const int* __restrict__ x, const float* __restrict__ h0,
    const float* __restrict__ emb, const float* __restrict__ Wh,
    const float* __restrict__ bh, float* __restrict__ final_h)
{
    __shared__ __align__(16) float s_emb[Vn * Hn];     // 20 KB
    __shared__ int s_x[2][Ln];                         // 8 KB
    __shared__ __align__(16) float s_h[2][2][Hn];      // [buf][row][elem]

    const int t  = threadIdx.x;
    const int b0 = blockIdx.x * 2;
    const int b1 = b0 + 1;

    for (int i = t; i < Vn * Hn; i += Hn) s_emb[i] = emb[i];
    for (int i = t; i < Ln; i += Hn) {
        s_x[0][i] = x[b0 * Ln + i];
        s_x[1][i] = x[b1 * Ln + i];
    }
    s_h[0][0][t] = h0[b0 * Hn + t];
    s_h[0][1][t] = h0[b1 * Hn + t];
    const float bh_t = bh[t];

    // Wh row t -> 64 packed pairs in registers (shared by both batch rows)
    unsigned long long wh[Hn / 2];
    const unsigned long long* wp = (const unsigned long long*)(Wh + t * Hn);
#pragma unroll
    for (int i = 0; i < Hn / 2; i++) wh[i] = wp[i];

    __syncthreads();

    float hn0 = s_h[0][0][t];
    float hn1 = s_h[0][1][t];
    float* o0 = g_hseq + (size_t)b0 * Ln * Hn + t;
    float* o1 = g_hseq + (size_t)b1 * Ln * Hn + t;

#pragma unroll 1
    for (int l = 0; l < Ln; l++) {
        const int i0 = s_x[0][l];
        const int i1 = s_x[1][l];
        const float e0 = s_emb[i0 * Hn + t];
        const float e1 = s_emb[i1 * Hn + t];

        const ulonglong2* hp0 = (const ulonglong2*)s_h[l & 1][0];
        const ulonglong2* hp1 = (const ulonglong2*)s_h[l & 1][1];

        unsigned long long a0 = 0, a1 = 0, a2 = 0, a3 = 0;   // row 0
        unsigned long long c0 = 0, c1 = 0, c2 = 0, c3 = 0;   // row 1
#pragma unroll
        for (int k = 0; k < Hn / 4; k += 2) {
            ulonglong2 p = hp0[k];          // LDS.128, broadcast
            ulonglong2 q = hp1[k];
            a0 = ffma2(wh[2 * k + 0], p.x, a0);
            c0 = ffma2(wh[2 * k + 0], q.x, c0);
            a1 = ffma2(wh[2 * k + 1], p.y, a1);
            c1 = ffma2(wh[2 * k + 1], q.y, c1);
            ulonglong2 p2 = hp0[k + 1];
            ulonglong2 q2 = hp1[k + 1];
            a2 = ffma2(wh[2 * k + 2], p2.x, a2);
            c2 = ffma2(wh[2 * k + 2], q2.x, c2);
            a3 = ffma2(wh[2 * k + 3], p2.y, a3);
            c3 = ffma2(wh[2 * k + 3], q2.y, c3);
        }
        a0 = add2(a0, a2);  c0 = add2(c0, c2);
        a1 = add2(a1, a3);  c1 = add2(c1, c3);
        a0 = add2(a0, a1);  c0 = add2(c0, c1);

        const float s0 = plo(a0) + phi(a0) + e0 + bh_t;
        const float s1 = plo(c0) + phi(c0) + e1 + bh_t;
        hn0 = tanh_fast(s0);
        hn1 = tanh_fast(s1);

        s_h[(l + 1) & 1][0][t] = hn0;
        s_h[(l + 1) & 1][1][t] = hn1;
        o0[(size_t)l * Hn] = hn0;           // coalesced 512B/step/row
        o1[(size_t)l * Hn] = hn1;
        __syncthreads();
    }

    final_h[b0 * Hn + t] = hn0;
    final_h[b1 * Hn + t] = hn1;
}

// =====================================================================
// Phase 2: logits[r, v] = sum_k hseq[r, k] * Wo[v, k] + b_y[v]
// V split into two 20-wide halves via blockIdx.y -> 20 u64 accumulators
// per thread (~70 regs) -> 3 CTAs/SM resident.
// =====================================================================
#define VH 20

__global__ void __launch_bounds__(256, 3) logits_kernel(
    const float* __restrict__ Wo, const float* __restrict__ by,
    float* __restrict__ out)
{
    __shared__ __align__(16) float s_wo[VH * Hn];      // 10 KB (one V-half)
    const int tid = threadIdx.x;
    const int v0  = blockIdx.y * VH;

    for (int i = tid; i < VH * Hn; i += 256) s_wo[i] = Wo[v0 * Hn + i];
    __syncthreads();

    const size_t r = (size_t)blockIdx.x * 256 + tid;
    const ulonglong2* h2 = (const ulonglong2*)(g_hseq + r * Hn);

    unsigned long long acc[VH];
#pragma unroll
    for (int v = 0; v < VH; v++) acc[v] = 0;

#pragma unroll 1
    for (int c = 0; c < 8; c++) {               // 8 chunks of 16 floats
        unsigned long long hh[8];
#pragma unroll
        for (int i = 0; i < 4; i++) {           // 4x LDG.128
            ulonglong2 p = h2[c * 4 + i];
            hh[2 * i]     = p.x;
            hh[2 * i + 1] = p.y;
        }
        const ulonglong2* wbase = (const ulonglong2*)(s_wo + c * 16);
#pragma unroll
        for (int v = 0; v < VH; v++) {
            const ulonglong2* w2 = wbase + (size_t)v * (Hn / 4);
            unsigned long long a = acc[v];
#pragma unroll
            for (int i = 0; i < 4; i++) {       // LDS.128 broadcast for Wo
                ulonglong2 w = w2[i];
                a = ffma2(hh[2 * i],     w.x, a);
                a = ffma2(hh[2 * i + 1], w.y, a);
            }
            acc[v] = a;
        }
    }

    // 20 outputs = 5 float4, base offset r*160 + v0*4 bytes (16B aligned)
    float4* o4 = (float4*)(out + r * Vn + v0);
#pragma unroll
    for (int j = 0; j < VH / 4; j++) {
        float4 o;
        o.x = plo(acc[4 * j + 0]) + phi(acc[4 * j + 0]) + by[v0 + 4 * j + 0];
        o.y = plo(acc[4 * j + 1]) + phi(acc[4 * j + 1]) + by[v0 + 4 * j + 1];
        o.z = plo(acc[4 * j + 2]) + phi(acc[4 * j + 2]) + by[v0 + 4 * j + 2];
        o.w = plo(acc[4 * j + 3]) + phi(acc[4 * j + 3]) + by[v0 + 4 * j + 3];
        o4[j] = o;
    }
}

extern "C" void kernel_launch(void* const* d_in, const int* in_sizes, int n_in,
                              void* d_out, int out_size)
{
    const int*   x   = (const int*)d_in[0];
    const float* h0  = (const float*)d_in[1];
    const float* emb = (const float*)d_in[2];
    const float* Wh  = (const float*)d_in[3];
    const float* Wo  = (const float*)d_in[4];
    const float* bh  = (const float*)d_in[5];
    const float* by  = (const float*)d_in[6];

    float* out     = (float*)d_out;
    float* logits  = out;                               // [B, L, V]
    float* final_h = out + (size_t)Bn * Ln * Vn;        // [B, H]

    rnn_scan_kernel<<<Bn / 2, Hn>>>(x, h0, emb, Wh, bh, final_h);

    dim3 grid2((Bn * Ln) / 256, Vn / VH);
    logits_kernel<<<grid2, 256>>>(Wo, by, logits);
}

// round 3
// speedup vs baseline: 1.6192x; 1.6192x over previous
#include <cuda_runtime.h>
#include <cstdint>
#include <cstddef>

#define Bn 256
#define Ln 1024
#define Vn 40
#define Hn 128

// 134 MB scratch for the hidden-state sequence [B, L, H] (alloc-free rule).
__device__ float g_hseq[(size_t)Bn * Ln * Hn];

// ---- packed f32x2 helpers (FFMA2 only reachable via PTX) ----
__device__ __forceinline__ unsigned long long ffma2(unsigned long long a,
                                                    unsigned long long b,
                                                    unsigned long long c) {
    unsigned long long d;
    asm("fma.rn.f32x2 %0, %1, %2, %3;" : "=l"(d) : "l"(a), "l"(b), "l"(c));
    return d;
}
__device__ __forceinline__ unsigned long long add2(unsigned long long a,
                                                   unsigned long long b) {
    unsigned long long d;
    asm("add.rn.f32x2 %0, %1, %2;" : "=l"(d) : "l"(a), "l"(b));
    return d;
}
__device__ __forceinline__ float plo(unsigned long long a) {
    return __int_as_float((int)(unsigned)(a & 0xffffffffull));
}
__device__ __forceinline__ float phi(unsigned long long a) {
    return __int_as_float((int)(unsigned)(a >> 32));
}
__device__ __forceinline__ float tanh_fast(float x) {
    float r;
    asm("tanh.approx.f32 %0, %1;" : "=f"(r) : "f"(x));
    return r;
}

// =====================================================================
// Phase 1: recurrence. 256 CTAs (one batch row each), 128 threads.
// Thread t owns elements (t&63) and (t&63)+64, over HALF the k-range
// (kh = t>>6). Each LDS.128 of h feeds 4 FFMA2 (2 elems x 2 pairs).
// Half-partials combined via one smem float2 exchange per step.
// =====================================================================
__global__ void __launch_bounds__(128, 2) rnn_scan_kernel(
    const int* __restrict__ x, const float* __restrict__ h0,
    const float* __restrict__ emb, const float* __restrict__ Wh,
    const float* __restrict__ bh, float* __restrict__ final_h)
{
    __shared__ __align__(16) float s_emb[Vn * Hn];   // 20 KB
    __shared__ int s_x[Ln];                          // 4 KB
    __shared__ __align__(16) float s_h[2][Hn];       // ping-pong h
    __shared__ __align__(8) float2 s_red[Hn];        // half-k partials

    const int t  = threadIdx.x;
    const int b  = blockIdx.x;
    const int e0 = t & 63;         // first owned element
    const int kh = t >> 6;         // which k-half this thread sums

    for (int i = t; i < Vn * Hn; i += 128) s_emb[i] = emb[i];
    for (int i = t; i < Ln; i += 128) s_x[i] = x[b * Ln + i];
    s_h[0][t] = h0[b * Hn + t];
    const float bh0 = bh[e0];
    const float bh1 = bh[e0 + 64];

    // wh[0..31]: row e0, cols [64kh, 64kh+64); wh[32..63]: row e0+64
    unsigned long long wh[64];
    {
        const ulonglong2* w0 = (const ulonglong2*)(Wh + e0 * Hn + kh * 64);
        const ulonglong2* w1 = (const ulonglong2*)(Wh + (e0 + 64) * Hn + kh * 64);
#pragma unroll
        for (int i = 0; i < 16; i++) {
            ulonglong2 p = w0[i];
            wh[2 * i] = p.x; wh[2 * i + 1] = p.y;
        }
#pragma unroll
        for (int i = 0; i < 16; i++) {
            ulonglong2 p = w1[i];
            wh[32 + 2 * i] = p.x; wh[33 + 2 * i] = p.y;
        }
    }
    __syncthreads();

    float* orow = g_hseq + (size_t)b * Ln * Hn;

#pragma unroll 1
    for (int l = 0; l < Ln; l++) {
        // 64 floats of h for this thread's k-half, broadcast within warp
        const ulonglong2* hp = (const ulonglong2*)(s_h[l & 1]) + kh * 16;

        unsigned long long a0 = 0, a1 = 0, c0 = 0, c1 = 0;
#pragma unroll
        for (int i = 0; i < 16; i++) {
            ulonglong2 p = hp[i];               // LDS.128, feeds 4 FFMA2
            a0 = ffma2(wh[2 * i],      p.x, a0);
            c0 = ffma2(wh[32 + 2 * i], p.x, c0);
            a1 = ffma2(wh[2 * i + 1],  p.y, a1);
            c1 = ffma2(wh[33 + 2 * i], p.y, c1);
        }
        a0 = add2(a0, a1);
        c0 = add2(c0, c1);
        const float pe0 = plo(a0) + phi(a0);    // elem e0, k-half kh
        const float pe1 = plo(c0) + phi(c0);    // elem e0+64, k-half kh

        s_red[t] = make_float2(pe0, pe1);
        __syncthreads();

        if (t < 64) {                            // kh==0 threads finalize
            const float2 pr = s_red[t + 64];     // partner's k-half
            const int idx = s_x[l];
            const float h0n = tanh_fast(pe0 + pr.x + s_emb[idx * Hn + t] + bh0);
            const float h1n = tanh_fast(pe1 + pr.y + s_emb[idx * Hn + t + 64] + bh1);
            float* nh = s_h[(l + 1) & 1];
            nh[t]      = h0n;
            nh[t + 64] = h1n;
            orow[(size_t)l * Hn + t]      = h0n;
            orow[(size_t)l * Hn + t + 64] = h1n;
        }
        __syncthreads();
    }

    final_h[b * Hn + t] = s_h[0][t];   // Ln even -> final state in buffer 0
}

// =====================================================================
// Phase 2: logits = h_seq @ Wo^T + b_y.
// 2048 CTAs x 256 threads; thread computes a 2-row x 10-v microtile.
// Wo in padded smem (stride 132 -> conflict-free); h rows via LDG.128
// (4 lanes share each 16B -> single sector + broadcast). h read ONCE.
// =====================================================================
#define TR 128   // rows per CTA

__global__ void __launch_bounds__(256, 2) logits_kernel(
    const float* __restrict__ Wo, const float* __restrict__ by,
    float* __restrict__ out)
{
    __shared__ __align__(16) float s_w[Vn * 132];    // 21.1 KB padded
    const int tid = threadIdx.x;

    for (int i = tid; i < Vn * Hn; i += 256) {
        int v = i >> 7, k = i & 127;
        s_w[v * 132 + k] = Wo[i];
    }
    __syncthreads();

    const int rp = tid >> 2;                 // 0..63
    const int vb = (tid & 3) * 10;           // 0,10,20,30
    const size_t rA = (size_t)blockIdx.x * TR + rp;
    const size_t rB = rA + 64;
    const ulonglong2* hA = (const ulonglong2*)(g_hseq + rA * Hn);
    const ulonglong2* hB = (const ulonglong2*)(g_hseq + rB * Hn);

    float bys[10];
#pragma unroll
    for (int v = 0; v < 10; v++) bys[v] = by[vb + v];

    unsigned long long aA[10], aB[10];
#pragma unroll
    for (int v = 0; v < 10; v++) { aA[v] = 0; aB[v] = 0; }

    ulonglong2 pa = hA[0];
    ulonglong2 pb = hB[0];
#pragma unroll 1
    for (int c = 0; c < 32; c++) {
        ulonglong2 na = pa, nb2 = pb;
        if (c < 31) { na = hA[c + 1]; nb2 = hB[c + 1]; }   // prefetch
        const float* wrow = s_w + vb * 132;
#pragma unroll
        for (int v = 0; v < 10; v++) {
            ulonglong2 pw = ((const ulonglong2*)(wrow + v * 132))[c];
            aA[v] = ffma2(pa.y, pw.y, ffma2(pa.x, pw.x, aA[v]));
            aB[v] = ffma2(pb.y, pw.y, ffma2(pb.x, pw.x, aB[v]));
        }
        pa = na; pb = nb2;
    }

    float2* oA = (float2*)(out + rA * Vn + vb);
    float2* oB = (float2*)(out + rB * Vn + vb);
#pragma unroll
    for (int j = 0; j < 5; j++) {
        float2 o;
        o.x = plo(aA[2 * j])     + phi(aA[2 * j])     + bys[2 * j];
        o.y = plo(aA[2 * j + 1]) + phi(aA[2 * j + 1]) + bys[2 * j + 1];
        oA[j] = o;
        o.x = plo(aB[2 * j])     + phi(aB[2 * j])     + bys[2 * j];
        o.y = plo(aB[2 * j + 1]) + phi(aB[2 * j + 1]) + bys[2 * j + 1];
        oB[j] = o;
    }
}

extern "C" void kernel_launch(void* const* d_in, const int* in_sizes, int n_in,
                              void* d_out, int out_size)
{
    const int*   x   = (const int*)d_in[0];
    const float* h0  = (const float*)d_in[1];
    const float* emb = (const float*)d_in[2];
    const float* Wh  = (const float*)d_in[3];
    const float* Wo  = (const float*)d_in[4];
    const float* bh  = (const float*)d_in[5];
    const float* by  = (const float*)d_in[6];

    float* out     = (float*)d_out;
    float* logits  = out;                               // [B, L, V]
    float* final_h = out + (size_t)Bn * Ln * Vn;        // [B, H]

    rnn_scan_kernel<<<Bn, 128>>>(x, h0, emb, Wh, bh, final_h);
    logits_kernel<<<(Bn * Ln) / TR, 256>>>(Wo, by, logits);
}

// round 5
// speedup vs baseline: 1.8767x; 1.1590x over previous
#include <cuda_runtime.h>
#include <cstdint>
#include <cstddef>

#define Bn 256
#define Ln 1024
#define Vn 40
#define Hn 128

// ---- packed f32x2 helpers (FFMA2 only reachable via PTX) ----
__device__ __forceinline__ unsigned long long ffma2(unsigned long long a,
                                                    unsigned long long b,
                                                    unsigned long long c) {
    unsigned long long d;
    asm("fma.rn.f32x2 %0, %1, %2, %3;" : "=l"(d) : "l"(a), "l"(b), "l"(c));
    return d;
}
__device__ __forceinline__ unsigned long long add2(unsigned long long a,
                                                   unsigned long long b) {
    unsigned long long d;
    asm("add.rn.f32x2 %0, %1, %2;" : "=l"(d) : "l"(a), "l"(b));
    return d;
}
__device__ __forceinline__ float plo(unsigned long long a) {
    return __int_as_float((int)(unsigned)(a & 0xffffffffull));
}
__device__ __forceinline__ float phi(unsigned long long a) {
    return __int_as_float((int)(unsigned)(a >> 32));
}
__device__ __forceinline__ float tanh_fast(float x) {
    float r;
    asm("tanh.approx.f32 %0, %1;" : "=f"(r) : "f"(x));
    return r;
}

// =====================================================================
// Fully fused CharRNN: one CTA per batch row, 128 threads.
// Scan: thread t computes partials for h-elements (t&63) and (t&63)+64
//       over k-half (t>>6); halves combined via smem exchange.
// Logits: interleaved into the same FFMA block, reusing the SAME h
//       registers. IMPORTANT: the h loaded at iteration l is the OUTPUT
//       of step l-1, so the logit computed at iteration l belongs to
//       output row l-1 (skip at l=0; emit row Ln-1 in an epilogue).
// Threads 64..103 finalize+store logits during the tail while threads
// 0..63 finalize h -> tail bubbles filled. No h_seq scratch, no second
// kernel, no 268 MB DRAM round trip.
// =====================================================================
__global__ void __launch_bounds__(128, 2) fused_rnn_kernel(
    const int* __restrict__ x, const float* __restrict__ h0,
    const float* __restrict__ emb, const float* __restrict__ Wh,
    const float* __restrict__ Wo, const float* __restrict__ bh,
    const float* __restrict__ by, float* __restrict__ out,
    float* __restrict__ final_h)
{
    __shared__ __align__(16) float s_emb[Vn * Hn];   // 20 KB
    __shared__ int s_x[Ln];                          // 4 KB
    __shared__ __align__(16) float s_h[2][Hn];       // ping-pong h
    __shared__ __align__(16) float4 s_red[128];      // {pe0, pe1, logit_partial, -}

    const int t  = threadIdx.x;
    const int b  = blockIdx.x;
    const int e0 = t & 63;         // owned h-elements e0, e0+64; logit v = e0
    const int kh = t >> 6;         // k-half this thread sums

    for (int i = t; i < Vn * Hn; i += 128) s_emb[i] = emb[i];
    for (int i = t; i < Ln; i += 128) s_x[i] = x[b * Ln + i];
    s_h[0][t] = h0[b * Hn + t];
    const float bh0 = bh[e0];
    const float bh1 = bh[e0 + 64];
    const bool  dv  = (e0 < Vn);
    const float byv = dv ? by[e0] : 0.f;

    // wh[0..31]: Wh row e0, cols [64kh,64kh+64); wh[32..63]: row e0+64
    unsigned long long wh[64];
    {
        const ulonglong2* w0 = (const ulonglong2*)(Wh + e0 * Hn + kh * 64);
        const ulonglong2* w1 = (const ulonglong2*)(Wh + (e0 + 64) * Hn + kh * 64);
#pragma unroll
        for (int i = 0; i < 16; i++) {
            ulonglong2 p = w0[i];
            wh[2 * i] = p.x; wh[2 * i + 1] = p.y;
        }
#pragma unroll
        for (int i = 0; i < 16; i++) {
            ulonglong2 p = w1[i];
            wh[32 + 2 * i] = p.x; wh[33 + 2 * i] = p.y;
        }
    }
    // wo[0..31]: Wo row v=e0, cols [64kh, 64kh+64) (zeros if v >= 40)
    unsigned long long wo[32];
    if (dv) {
        const ulonglong2* wv = (const ulonglong2*)(Wo + e0 * Hn + kh * 64);
#pragma unroll
        for (int i = 0; i < 16; i++) {
            ulonglong2 p = wv[i];
            wo[2 * i] = p.x; wo[2 * i + 1] = p.y;
        }
    } else {
#pragma unroll
        for (int i = 0; i < 32; i++) wo[i] = 0ull;
    }
    __syncthreads();

    float* obase = out + (size_t)b * Ln * Vn;

#pragma unroll 1
    for (int l = 0; l < Ln; l++) {
        const int idx = s_x[l];
        // h entering step l == output of step l-1 (broadcast within warp)
        const ulonglong2* hp = (const ulonglong2*)(s_h[l & 1]) + kh * 16;

        unsigned long long a0 = 0, a1 = 0;   // h elem e0
        unsigned long long c0 = 0, c1 = 0;   // h elem e0+64
        unsigned long long g0 = 0, g1 = 0;   // logit v = e0 (for row l-1)
#pragma unroll
        for (int i = 0; i < 16; i++) {
            ulonglong2 p = hp[i];            // LDS.128 -> feeds 6 FFMA2
            a0 = ffma2(wh[2 * i],      p.x, a0);
            c0 = ffma2(wh[32 + 2 * i], p.x, c0);
            g0 = ffma2(wo[2 * i],      p.x, g0);
            a1 = ffma2(wh[2 * i + 1],  p.y, a1);
            c1 = ffma2(wh[33 + 2 * i], p.y, c1);
            g1 = ffma2(wo[2 * i + 1],  p.y, g1);
        }
        a0 = add2(a0, a1);
        c0 = add2(c0, c1);
        g0 = add2(g0, g1);
        const float pe0 = plo(a0) + phi(a0);
        const float pe1 = plo(c0) + phi(c0);
        const float lp  = plo(g0) + phi(g0);

        // prefetch embedding terms (only t<64 uses them; harmless elsewhere)
        const float em0 = s_emb[idx * Hn + e0];
        const float em1 = s_emb[idx * Hn + e0 + 64];

        s_red[t] = make_float4(pe0, pe1, lp, 0.f);
        __syncthreads();

        if (t < 64) {                        // finalize h (both halves)
            const float4 pr = s_red[t + 64];
            const float h0n = tanh_fast(pe0 + pr.x + em0 + bh0);
            const float h1n = tanh_fast(pe1 + pr.y + em1 + bh1);
            float* nh = s_h[(l + 1) & 1];
            nh[t]      = h0n;
            nh[t + 64] = h1n;
        } else if (dv && l > 0) {            // logit row l-1 (from h_{l-1})
            const float other = s_red[e0].z; // kh=0 partial from thread e0
            obase[(size_t)(l - 1) * Vn + e0] = lp + other + byv;
        }
        __syncthreads();
    }

    // Epilogue: logits for the final step (row Ln-1) from s_h[0] (final h).
    {
        const ulonglong2* hp = (const ulonglong2*)(s_h[0]) + kh * 16;
        unsigned long long g0 = 0, g1 = 0;
#pragma unroll
        for (int i = 0; i < 16; i++) {
            ulonglong2 p = hp[i];
            g0 = ffma2(wo[2 * i],     p.x, g0);
            g1 = ffma2(wo[2 * i + 1], p.y, g1);
        }
        g0 = add2(g0, g1);
        const float lp = plo(g0) + phi(g0);
        s_red[t].z = lp;
        __syncthreads();
        if (t >= 64 && dv) {
            const float other = s_red[e0].z;
            obase[(size_t)(Ln - 1) * Vn + e0] = lp + other + byv;
        }
    }

    final_h[b * Hn + t] = s_h[0][t];   // Ln even -> final state in buffer 0
}

extern "C" void kernel_launch(void* const* d_in, const int* in_sizes, int n_in,
                              void* d_out, int out_size)
{
    const int*   x   = (const int*)d_in[0];
    const float* h0  = (const float*)d_in[1];
    const float* emb = (const float*)d_in[2];
    const float* Wh  = (const float*)d_in[3];
    const float* Wo  = (const float*)d_in[4];
    const float* bh  = (const float*)d_in[5];
    const float* by  = (const float*)d_in[6];

    float* out     = (float*)d_out;
    float* logits  = out;                               // [B, L, V]
    float* final_h = out + (size_t)Bn * Ln * Vn;        // [B, H]

    fused_rnn_kernel<<<Bn, 128>>>(x, h0, emb, Wh, Wo, bh, by, logits, final_h);
}

// round 7
// speedup vs baseline: 1.9711x; 1.0503x over previous
#include <cuda_runtime.h>
#include <cstdint>
#include <cstddef>

#define Bn 256
#define Ln 1024
#define Vn 40
#define Hn 128

// ---- packed f32x2 helpers (FFMA2 only reachable via PTX) ----
__device__ __forceinline__ unsigned long long ffma2(unsigned long long a,
                                                    unsigned long long b,
                                                    unsigned long long c) {
    unsigned long long d;
    asm("fma.rn.f32x2 %0, %1, %2, %3;" : "=l"(d) : "l"(a), "l"(b), "l"(c));
    return d;
}
__device__ __forceinline__ unsigned long long add2(unsigned long long a,
                                                   unsigned long long b) {
    unsigned long long d;
    asm("add.rn.f32x2 %0, %1, %2;" : "=l"(d) : "l"(a), "l"(b));
    return d;
}
__device__ __forceinline__ float plo(unsigned long long a) {
    return __int_as_float((int)(unsigned)(a & 0xffffffffull));
}
__device__ __forceinline__ float phi(unsigned long long a) {
    return __int_as_float((int)(unsigned)(a >> 32));
}
__device__ __forceinline__ float tanh_fast(float x) {
    float r;
    asm("tanh.approx.f32 %0, %1;" : "=f"(r) : "f"(x));
    return r;
}

// =====================================================================
// Fused CharRNN, symmetric-finalize version. One CTA per batch row.
// Thread t: e0 = t&63, kh = t>>6 (warp-uniform). Computes half-k
// partials for h elems e0, e0+64 and logit v=e0 (zero-padded v>=40).
// kh=0 threads fold em+bh into their partials pre-exchange; after one
// barrier EVERY thread finalizes exactly elem t: 1 LDS.32 + 1 FADD +
// tanh + coalesced STS.32. Logit rows shifted: iteration l emits row
// l-1 (h loaded at iter l is the output of step l-1); row Ln-1 in an
// epilogue. Embedding terms register-prefetched one step ahead.
// =====================================================================
__global__ void __launch_bounds__(128, 2) fused_rnn_kernel(
    const int* __restrict__ x, const float* __restrict__ h0,
    const float* __restrict__ emb, const float* __restrict__ Wh,
    const float* __restrict__ Wo, const float* __restrict__ bh,
    const float* __restrict__ by, float* __restrict__ out,
    float* __restrict__ final_h)
{
    __shared__ __align__(16) float s_emb[Vn * Hn];   // 20 KB
    __shared__ int s_x[Ln];                          // 4 KB
    __shared__ __align__(16) float s_h[2][Hn];       // ping-pong h
    __shared__ __align__(16) float4 s_red[128];      // {pe0, pe1, lp, -}

    const int t  = threadIdx.x;
    const int b  = blockIdx.x;
    const int e0 = t & 63;
    const int kh = t >> 6;                            // warp-uniform

    for (int i = t; i < Vn * Hn; i += 128) s_emb[i] = emb[i];
    for (int i = t; i < Ln; i += 128) s_x[i] = x[b * Ln + i];
    s_h[0][t] = h0[b * Hn + t];
    const float bh0 = bh[e0];
    const float bh1 = bh[e0 + 64];
    const bool  dv  = (e0 < Vn);
    const float byv = dv ? by[e0] : 0.f;

    // wh[0..31]: Wh row e0, cols [64kh,64kh+64); wh[32..63]: row e0+64
    unsigned long long wh[64];
    {
        const ulonglong2* w0 = (const ulonglong2*)(Wh + e0 * Hn + kh * 64);
        const ulonglong2* w1 = (const ulonglong2*)(Wh + (e0 + 64) * Hn + kh * 64);
#pragma unroll
        for (int i = 0; i < 16; i++) {
            ulonglong2 p = w0[i];
            wh[2 * i] = p.x; wh[2 * i + 1] = p.y;
        }
#pragma unroll
        for (int i = 0; i < 16; i++) {
            ulonglong2 p = w1[i];
            wh[32 + 2 * i] = p.x; wh[33 + 2 * i] = p.y;
        }
    }
    // wo[0..31]: Wo row v=e0, cols [64kh,64kh+64) (zeros if v >= 40)
    unsigned long long wo[32];
    if (dv) {
        const ulonglong2* wv = (const ulonglong2*)(Wo + e0 * Hn + kh * 64);
#pragma unroll
        for (int i = 0; i < 16; i++) {
            ulonglong2 p = wv[i];
            wo[2 * i] = p.x; wo[2 * i + 1] = p.y;
        }
    } else {
#pragma unroll
        for (int i = 0; i < 32; i++) wo[i] = 0ull;
    }
    __syncthreads();

    float* obase = out + (size_t)b * Ln * Vn;

    // Prefetch embedding terms for step 0 (kh=0 warps only; warp-uniform)
    float em0c = 0.f, em1c = 0.f;
    if (kh == 0) {
        const int idx0 = s_x[0];
        em0c = s_emb[idx0 * Hn + e0];
        em1c = s_emb[idx0 * Hn + e0 + 64];
    }

#pragma unroll 1
    for (int l = 0; l < Ln; l++) {
        // h entering step l == output of step l-1 (LDS.128 broadcast)
        const ulonglong2* hp = (const ulonglong2*)(s_h[l & 1]) + kh * 16;

        unsigned long long a0 = 0, a1 = 0;   // h elem e0
        unsigned long long c0 = 0, c1 = 0;   // h elem e0+64
        unsigned long long g0 = 0, g1 = 0;   // logit v=e0 (for row l-1)
#pragma unroll
        for (int i = 0; i < 16; i++) {
            ulonglong2 p = hp[i];            // LDS.128 -> feeds 6 FFMA2
            a0 = ffma2(wh[2 * i],      p.x, a0);
            c0 = ffma2(wh[32 + 2 * i], p.x, c0);
            g0 = ffma2(wo[2 * i],      p.x, g0);
            a1 = ffma2(wh[2 * i + 1],  p.y, a1);
            c1 = ffma2(wh[33 + 2 * i], p.y, c1);
            g1 = ffma2(wo[2 * i + 1],  p.y, g1);
        }
        a0 = add2(a0, a1);
        c0 = add2(c0, c1);
        g0 = add2(g0, g1);
        float pe0 = plo(a0) + phi(a0);
        float pe1 = plo(c0) + phi(c0);
        const float lp = plo(g0) + phi(g0);

        if (kh == 0) {                        // fold em + bh exactly once
            pe0 += em0c + bh0;
            pe1 += em1c + bh1;
        }
        s_red[t] = make_float4(pe0, pe1, lp, 0.f);

        // Register-prefetch embedding terms for step l+1 (hidden by BAR)
        if (kh == 0) {
            const int idxn = s_x[(l + 1) & (Ln - 1)];
            em0c = s_emb[idxn * Hn + e0];
            em1c = s_emb[idxn * Hn + e0 + 64];
        }
        __syncthreads();                      // BAR1: partials published

        // Every thread finalizes elem t: mine + partner's half
        const float mine  = (kh == 0) ? pe0 : pe1;
        const float other = ((const float*)s_red)[((t ^ 64) << 2) + kh];
        const float hn = tanh_fast(mine + other);
        s_h[(l + 1) & 1][t] = hn;             // coalesced STS.32

        if (dv && kh == 0 && l > 0) {         // logit row l-1
            const float lp2 = s_red[t + 64].z;
            obase[(size_t)(l - 1) * Vn + e0] = lp + lp2 + byv;
        }
        __syncthreads();                      // BAR2: s_h/s_red safe
    }

    // Epilogue: logit row Ln-1 from the final hidden state (s_h[0]).
    {
        const ulonglong2* hp = (const ulonglong2*)(s_h[0]) + kh * 16;
        unsigned long long g0 = 0, g1 = 0;
#pragma unroll
        for (int i = 0; i < 16; i++) {
            ulonglong2 p = hp[i];
            g0 = ffma2(wo[2 * i],     p.x, g0);
            g1 = ffma2(wo[2 * i + 1], p.y, g1);
        }
        g0 = add2(g0, g1);
        const float lp = plo(g0) + phi(g0);
        s_red[t] = make_float4(0.f, 0.f, lp, 0.f);
        __syncthreads();
        if (dv && kh == 0) {
            const float lp2 = s_red[t + 64].z;
            obase[(size_t)(Ln - 1) * Vn + e0] = lp + lp2 + byv;
        }
    }

    final_h[b * Hn + t] = s_h[0][t];   // Ln even -> final state in buffer 0
}

extern "C" void kernel_launch(void* const* d_in, const int* in_sizes, int n_in,
                              void* d_out, int out_size)
{
    const int*   x   = (const int*)d_in[0];
    const float* h0  = (const float*)d_in[1];
    const float* emb = (const float*)d_in[2];
    const float* Wh  = (const float*)d_in[3];
    const float* Wo  = (const float*)d_in[4];
    const float* bh  = (const float*)d_in[5];
    const float* by  = (const float*)d_in[6];

    float* out     = (float*)d_out;
    float* logits  = out;                               // [B, L, V]
    float* final_h = out + (size_t)Bn * Ln * Vn;        // [B, H]

    fused_rnn_kernel<<<Bn, 128>>>(x, h0, emb, Wh, Wo, bh, by, logits, final_h);
}